// round 3
// baseline (speedup 1.0000x reference)
#include <cuda_runtime.h>

#define BB 128
#define SS 48
#define DD 8
#define HDD 8
#define LL 8
#define NCLS 7
#define NTOT (BB*SS*SS*DD)   // 2,359,296 floats = 9.4 MB

// Static scratch (allocation-free rule): h0 + 2x2 ping-pong axis outputs.
__device__ float g_h0[NTOT];
__device__ float g_row[2][NTOT];
__device__ float g_col[2][NTOT];

// ---------------------------------------------------------------------------
// Encoder: h0[b,i,j,d] = relu(x[b,i,j]*enc_w[d] + enc_b[d]) + pos_row[i,d] + pos_col[j,d]
// ---------------------------------------------------------------------------
__global__ __launch_bounds__(256) void encoder_kernel(
    const float* __restrict__ x,
    const float* __restrict__ enc_w,
    const float* __restrict__ enc_b,
    const float* __restrict__ pos_row,
    const float* __restrict__ pos_col)
{
    int idx = blockIdx.x * blockDim.x + threadIdx.x;   // (b,i,j)
    if (idx >= BB * SS * SS) return;
    int j = idx % SS;
    int i = (idx / SS) % SS;
    float xv = x[idx];
    float out[8];
#pragma unroll
    for (int d = 0; d < 8; d++) {
        float v = fmaxf(fmaf(xv, enc_w[d], enc_b[d]), 0.f);
        out[d] = v + pos_row[i * DD + d] + pos_col[j * DD + d];
    }
    float4* dst = (float4*)&g_h0[(size_t)idx * 8];
    dst[0] = make_float4(out[0], out[1], out[2], out[3]);
    dst[1] = make_float4(out[4], out[5], out[6], out[7]);
}

// ---------------------------------------------------------------------------
// One axial self-attention block.
// blockIdx = (slice, batch, axis). axis 0: attend over rows i (fixed j=slice);
// axis 1: attend over cols j (fixed i=slice). 96 threads; thread t = (h=t/48, i=t%48).
// Input = relu(g_row[in] + g_col[in]) (or g_h0 for layer 0), fused at load.
// ---------------------------------------------------------------------------
__global__ __launch_bounds__(96) void layer_kernel(
    int in_mode,        // 0: read g_h0; 1/2: read g_row/g_col[in_mode-1]
    int out_sel,
    const float* __restrict__ Wq_all, const float* __restrict__ Wk_all,
    const float* __restrict__ Wv_all, const float* __restrict__ Wo_all,
    const float* __restrict__ bo_all, int layer)
{
    const int slice = blockIdx.x;
    const int b     = blockIdx.y;
    const int axis  = blockIdx.z;
    const int t     = threadIdx.x;

    __shared__ float Xs[SS][DD];
    __shared__ float Qs[SS][DD];
    __shared__ float Ks[SS][DD];
    __shared__ float Vs[SS][DD];
    __shared__ float Os[SS][DD];
    __shared__ float Wsm[3][HDD][DD];   // Wq(*0.5), Wk, Wv
    __shared__ float Wos[DD][HDD];
    __shared__ float bos[DD];

    const int wofs = (layer * 2 + axis) * 64;

    // Weights -> smem (fold E^-0.5 = 0.5 into Wq)
    for (int k = t; k < 3 * 64; k += 96) {
        int m = k >> 6, r = k & 63;
        const float* src = (m == 0) ? Wq_all : (m == 1) ? Wk_all : Wv_all;
        float v = src[wofs + r];
        if (m == 0) v *= 0.5f;
        ((float*)Wsm)[k] = v;
    }
    if (t < 64) ((float*)Wos)[t] = Wo_all[wofs + t];
    if (t >= 64 && t < 64 + DD) bos[t - 64] = bo_all[(layer * 2 + axis) * DD + (t - 64)];

    // X slice -> smem with fused relu(row+col) combine
    const int base = b * (SS * SS * DD);
    const float* inR = (in_mode == 0) ? g_h0 : g_row[in_mode - 1];
    const float* inC = (in_mode == 0) ? g_h0 : g_col[in_mode - 1];
    for (int k = t; k < SS * DD; k += 96) {
        int tok = k >> 3, d = k & 7;
        int addr = (axis == 0) ? base + (tok * SS + slice) * DD + d
                               : base + (slice * SS + tok) * DD + d;
        float v;
        if (in_mode == 0) v = inR[addr];
        else              v = fmaxf(inR[addr] + inC[addr], 0.f);
        Xs[tok][d] = v;
    }
    __syncthreads();

    // Q,K,V projections: 3*48*8 outputs, 8-MAC dot each
    for (int k = t; k < 3 * SS * DD; k += 96) {
        int m = k / 384;
        int r = k - m * 384;
        int tok = r >> 3, hd = r & 7;
        const float* w  = &Wsm[m][hd][0];
        const float* xr = &Xs[tok][0];
        float acc = 0.f;
#pragma unroll
        for (int d = 0; d < 8; d++) acc = fmaf(xr[d], w[d], acc);
        float* dst = (m == 0) ? &Qs[0][0] : (m == 1) ? &Ks[0][0] : &Vs[0][0];
        dst[r] = acc;
    }
    __syncthreads();

    // Attention core: one (h, i) row per thread; dots/softmax/o fully in registers.
    {
        const int h = t / SS;           // 0..1
        const int i = t - h * SS;       // 0..47
        const float4 q = *(const float4*)&Qs[i][h * 4];
        float a[SS];
        float mx = -1e30f;
#pragma unroll
        for (int j = 0; j < SS; j++) {
            float4 kk = *(const float4*)&Ks[j][h * 4];
            float dv = q.x * kk.x + q.y * kk.y + q.z * kk.z + q.w * kk.w;
            a[j] = dv;
            mx = fmaxf(mx, dv);
        }
        float s = 0.f;
#pragma unroll
        for (int j = 0; j < SS; j++) { float e = __expf(a[j] - mx); a[j] = e; s += e; }
        float inv = 1.f / s;
        float o0 = 0.f, o1 = 0.f, o2 = 0.f, o3 = 0.f;
#pragma unroll
        for (int j = 0; j < SS; j++) {
            float4 vv = *(const float4*)&Vs[j][h * 4];
            o0 = fmaf(a[j], vv.x, o0);
            o1 = fmaf(a[j], vv.y, o1);
            o2 = fmaf(a[j], vv.z, o2);
            o3 = fmaf(a[j], vv.w, o3);
        }
        Os[i][h * 4 + 0] = o0 * inv;
        Os[i][h * 4 + 1] = o1 * inv;
        Os[i][h * 4 + 2] = o2 * inv;
        Os[i][h * 4 + 3] = o3 * inv;
    }
    __syncthreads();

    // Output projection + store
    float* outbuf = (axis == 0) ? g_row[out_sel] : g_col[out_sel];
    for (int k = t; k < SS * DD; k += 96) {
        int tok = k >> 3, d = k & 7;
        const float* orow = &Os[tok][0];
        const float* w    = &Wos[d][0];
        float acc = bos[d];
#pragma unroll
        for (int e = 0; e < 8; e++) acc = fmaf(orow[e], w[e], acc);
        int addr = (axis == 0) ? base + (tok * SS + slice) * DD + d
                               : base + (slice * SS + tok) * DD + d;
        outbuf[addr] = acc;
    }
}

// ---------------------------------------------------------------------------
// Classifier: m[b,i,j] = relu(max_d(o_row+o_col)); logits = m @ cls_w.T + cls_b; softmax
// One block per batch.
// ---------------------------------------------------------------------------
__global__ __launch_bounds__(256) void cls_kernel(
    const float* __restrict__ cls_w, const float* __restrict__ cls_b,
    float* __restrict__ out, int sel)
{
    const int b = blockIdx.x;
    const int t = threadIdx.x;
    const float* r = g_row[sel];
    const float* c = g_col[sel];
    const int base = b * SS * SS * DD;

    float part[NCLS];
#pragma unroll
    for (int cc = 0; cc < NCLS; cc++) part[cc] = 0.f;

    for (int k = t; k < SS * SS; k += 256) {
        const float4* pr = (const float4*)&r[base + k * 8];
        const float4* pc = (const float4*)&c[base + k * 8];
        float4 r0 = pr[0], r1 = pr[1], c0 = pc[0], c1 = pc[1];
        float m = fmaxf(fmaxf(fmaxf(r0.x + c0.x, r0.y + c0.y), fmaxf(r0.z + c0.z, r0.w + c0.w)),
                        fmaxf(fmaxf(r1.x + c1.x, r1.y + c1.y), fmaxf(r1.z + c1.z, r1.w + c1.w)));
        m = fmaxf(m, 0.f);   // max_d relu == relu max_d (relu monotone)
#pragma unroll
        for (int cc = 0; cc < NCLS; cc++)
            part[cc] = fmaf(m, cls_w[cc * (SS * SS) + k], part[cc]);
    }

    __shared__ float red[NCLS][256];
#pragma unroll
    for (int cc = 0; cc < NCLS; cc++) red[cc][t] = part[cc];
    __syncthreads();
    for (int off = 128; off > 0; off >>= 1) {
        if (t < off) {
#pragma unroll
            for (int cc = 0; cc < NCLS; cc++) red[cc][t] += red[cc][t + off];
        }
        __syncthreads();
    }
    if (t == 0) {
        float lg[NCLS];
        float mx = -1e30f;
#pragma unroll
        for (int cc = 0; cc < NCLS; cc++) {
            lg[cc] = red[cc][0] + cls_b[cc];
            mx = fmaxf(mx, lg[cc]);
        }
        float s = 0.f;
#pragma unroll
        for (int cc = 0; cc < NCLS; cc++) { lg[cc] = __expf(lg[cc] - mx); s += lg[cc]; }
        float inv = 1.f / s;
#pragma unroll
        for (int cc = 0; cc < NCLS; cc++) out[b * NCLS + cc] = lg[cc] * inv;
    }
}

// ---------------------------------------------------------------------------
extern "C" void kernel_launch(void* const* d_in, const int* in_sizes, int n_in,
                              void* d_out, int out_size)
{
    (void)in_sizes; (void)n_in; (void)out_size;
    const float* x       = (const float*)d_in[0];
    const float* enc_w   = (const float*)d_in[1];
    const float* enc_b   = (const float*)d_in[2];
    const float* pos_row = (const float*)d_in[3];
    const float* pos_col = (const float*)d_in[4];
    const float* Wq      = (const float*)d_in[5];
    const float* Wk      = (const float*)d_in[6];
    const float* Wv      = (const float*)d_in[7];
    const float* Wo      = (const float*)d_in[8];
    const float* bo      = (const float*)d_in[9];
    const float* cls_w   = (const float*)d_in[10];
    const float* cls_b   = (const float*)d_in[11];

    encoder_kernel<<<(BB * SS * SS + 255) / 256, 256>>>(x, enc_w, enc_b, pos_row, pos_col);

    dim3 grid(SS, BB, 2);
    for (int l = 0; l < LL; l++) {
        int in_mode = (l == 0) ? 0 : 1 + ((l - 1) & 1);
        int out_sel = l & 1;
        layer_kernel<<<grid, 96>>>(in_mode, out_sel, Wq, Wk, Wv, Wo, bo, l);
    }

    cls_kernel<<<BB, 256>>>(cls_w, cls_b, (float*)d_out, (LL - 1) & 1);
}

// round 7
// speedup vs baseline: 1.4175x; 1.4175x over previous
#include <cuda_runtime.h>

#define BB 128
#define SS 48
#define DD 8
#define HDD 8
#define LL 8
#define NCLS 7
#define NTOT (BB*SS*SS*DD)   // 2,359,296 floats = 9.4 MB

// Static scratch (allocation-free rule): h0 + 2x2 ping-pong axis outputs.
__device__ float g_h0[NTOT];
__device__ float g_row[2][NTOT];
__device__ float g_col[2][NTOT];

// ---------------- f32x2 packed-math helpers (Blackwell) ----------------
__device__ __forceinline__ float2 mk2(float a, float b) { return make_float2(a, b); }

__device__ __forceinline__ float2 mul2(float2 a, float2 b) {
    float2 r;
    asm("mul.rn.f32x2 %0, %1, %2;"
        : "=l"(reinterpret_cast<unsigned long long&>(r))
        : "l"(reinterpret_cast<const unsigned long long&>(a)),
          "l"(reinterpret_cast<const unsigned long long&>(b)));
    return r;
}
__device__ __forceinline__ float2 fma2(float2 a, float2 b, float2 c) {
    float2 r;
    asm("fma.rn.f32x2 %0, %1, %2, %3;"
        : "=l"(reinterpret_cast<unsigned long long&>(r))
        : "l"(reinterpret_cast<const unsigned long long&>(a)),
          "l"(reinterpret_cast<const unsigned long long&>(b)),
          "l"(reinterpret_cast<const unsigned long long&>(c)));
    return r;
}
__device__ __forceinline__ float ex2f(float x) {
    float r; asm("ex2.approx.f32 %0, %1;" : "=f"(r) : "f"(x)); return r;
}

// ---------------------------------------------------------------------------
// Encoder: h0[b,i,j,d] = relu(x[b,i,j]*enc_w[d] + enc_b[d]) + pos_row[i,d] + pos_col[j,d]
// ---------------------------------------------------------------------------
__global__ __launch_bounds__(256) void encoder_kernel(
    const float* __restrict__ x,
    const float* __restrict__ enc_w,
    const float* __restrict__ enc_b,
    const float* __restrict__ pos_row,
    const float* __restrict__ pos_col)
{
    int idx = blockIdx.x * blockDim.x + threadIdx.x;   // (b,i,j)
    if (idx >= BB * SS * SS) return;
    int j = idx % SS;
    int i = (idx / SS) % SS;
    float xv = x[idx];
    float out[8];
#pragma unroll
    for (int d = 0; d < 8; d++) {
        float v = fmaxf(fmaf(xv, enc_w[d], enc_b[d]), 0.f);
        out[d] = v + pos_row[i * DD + d] + pos_col[j * DD + d];
    }
    float4* dst = (float4*)&g_h0[(size_t)idx * 8];
    dst[0] = make_float4(out[0], out[1], out[2], out[3]);
    dst[1] = make_float4(out[4], out[5], out[6], out[7]);
}

// ---------------------------------------------------------------------------
// One axial self-attention block.  blockIdx = (slice, batch, axis).
// 96 threads; core: thread t = (h = t/48, query i = t%48).
// K/V live in SMEM in j-pair-interleaved layout for f32x2 (FFMA2) math;
// Q is stored duplicated (q_e,q_e) so dot products run two keys per FFMA2.
// ---------------------------------------------------------------------------
__global__ __launch_bounds__(96, 8) void layer_kernel(
    int in_mode,        // 0: read g_h0; 1/2: read g_row/g_col[in_mode-1]
    int out_sel,
    const float* __restrict__ Wq_all, const float* __restrict__ Wk_all,
    const float* __restrict__ Wv_all, const float* __restrict__ Wo_all,
    const float* __restrict__ bo_all, int layer)
{
    const int slice = blockIdx.x;
    const int b     = blockIdx.y;
    const int axis  = blockIdx.z;
    const int t     = threadIdx.x;

    __shared__ __align__(16) float Xs[SS][DD];
    __shared__ __align__(16) float Qd[2][SS][8];    // [h][i][e*2+c], c in {0,1} duplicate
    __shared__ __align__(16) float Kp[2][24][8];    // [h][j/2][e*2 + (j&1)]
    __shared__ __align__(16) float Vp[2][24][8];    // same pair layout as Kp
    __shared__ __align__(16) float Os[SS][DD];
    __shared__ __align__(16) float Wsm[3][HDD][DD]; // Wq(*0.5), Wk, Wv
    __shared__ __align__(16) float Wos[DD][HDD];
    __shared__ float bos[DD];

    const int wofs = (layer * 2 + axis) * 64;

    // Weights -> smem (fold E^-0.5 = 0.5 into Wq)
    for (int k = t; k < 3 * 64; k += 96) {
        int m = k >> 6, r = k & 63;
        const float* src = (m == 0) ? Wq_all : (m == 1) ? Wk_all : Wv_all;
        float v = src[wofs + r];
        if (m == 0) v *= 0.5f;
        ((float*)Wsm)[k] = v;
    }
    if (t < 64) ((float*)Wos)[t] = Wo_all[wofs + t];
    else if (t < 64 + DD) bos[t - 64] = bo_all[(layer * 2 + axis) * DD + (t - 64)];

    // X slice -> smem with fused relu(row+col) combine.  One half-token (float4)/thread.
    const int base = b * (SS * SS * DD);
    {
        const int tok = t >> 1, hf = (t & 1) * 4;
        const int addr = (axis == 0) ? base + (tok * SS + slice) * DD + hf
                                     : base + (slice * SS + tok) * DD + hf;
        if (in_mode == 0) {
            *(float4*)&Xs[tok][hf] = *(const float4*)&g_h0[addr];
        } else {
            const float* inR = g_row[in_mode - 1];
            const float* inC = g_col[in_mode - 1];
            float4 rv = *(const float4*)&inR[addr];
            float4 cv = *(const float4*)&inC[addr];
            rv.x = fmaxf(rv.x + cv.x, 0.f);
            rv.y = fmaxf(rv.y + cv.y, 0.f);
            rv.z = fmaxf(rv.z + cv.z, 0.f);
            rv.w = fmaxf(rv.w + cv.w, 0.f);
            *(float4*)&Xs[tok][hf] = rv;
        }
    }
    __syncthreads();

    // Q,K,V projections: 12 outputs/thread, all-LDS.128 f32x2 dots.
#pragma unroll
    for (int m = 0; m < 3; m++) {
#pragma unroll
        for (int it = 0; it < 4; it++) {
            const int r   = it * 96 + t;       // 0..383 within this m
            const int tok = r >> 3, hd = r & 7;
            const float4* xr = (const float4*)Xs[tok];
            const float4* wr = (const float4*)Wsm[m][hd];
            float4 xa = xr[0], xb = xr[1], wa = wr[0], wb = wr[1];
            float2 acc = mul2(mk2(xa.x, xa.y), mk2(wa.x, wa.y));
            acc = fma2(mk2(xa.z, xa.w), mk2(wa.z, wa.w), acc);
            acc = fma2(mk2(xb.x, xb.y), mk2(wb.x, wb.y), acc);
            acc = fma2(mk2(xb.z, xb.w), mk2(wb.z, wb.w), acc);
            float v = acc.x + acc.y;
            const int h = hd >> 2, e = hd & 3;
            if (m == 0) {                       // Q duplicated
                Qd[h][tok][e * 2]     = v;
                Qd[h][tok][e * 2 + 1] = v;
            } else if (m == 1) {                // K pair-interleaved
                Kp[h][tok >> 1][e * 2 + (tok & 1)] = v;
            } else {                            // V pair-interleaved
                Vp[h][tok >> 1][e * 2 + (tok & 1)] = v;
            }
        }
    }
    __syncthreads();

    // Attention core: 2 keys per FFMA2 everywhere.
    {
        const int h = t / SS;
        const int i = t - h * SS;
        const float2* qp = (const float2*)Qd[h][i];
        const float2 q0 = qp[0], q1 = qp[1], q2 = qp[2], q3 = qp[3];

        float2 a2[24];
        float mx = -1e30f;
#pragma unroll
        for (int jp = 0; jp < 24; jp++) {
            const float4* kp = (const float4*)Kp[h][jp];
            float4 k01 = kp[0], k23 = kp[1];
            float2 acc = mul2(q0, mk2(k01.x, k01.y));
            acc = fma2(q1, mk2(k01.z, k01.w), acc);
            acc = fma2(q2, mk2(k23.x, k23.y), acc);
            acc = fma2(q3, mk2(k23.z, k23.w), acc);
            a2[jp] = acc;
            mx = fmaxf(mx, fmaxf(acc.x, acc.y));
        }

        const float L2E = 1.4426950408889634f;
        const float2 l2 = mk2(L2E, L2E);
        const float nb  = -mx * L2E;
        const float2 nb2 = mk2(nb, nb);
        float s = 0.f;
#pragma unroll
        for (int jp = 0; jp < 24; jp++) {
            float2 e = fma2(a2[jp], l2, nb2);   // (a - mx) * log2(e), packed
            e.x = ex2f(e.x);
            e.y = ex2f(e.y);
            a2[jp] = e;
            s += e.x + e.y;
        }
        const float inv = 1.f / s;

        float2 o0 = mk2(0.f, 0.f), o1 = o0, o2 = o0, o3 = o0;
#pragma unroll
        for (int jp = 0; jp < 24; jp++) {
            const float4* vp = (const float4*)Vp[h][jp];
            float4 v01 = vp[0], v23 = vp[1];
            float2 a = a2[jp];
            o0 = fma2(a, mk2(v01.x, v01.y), o0);
            o1 = fma2(a, mk2(v01.z, v01.w), o1);
            o2 = fma2(a, mk2(v23.x, v23.y), o2);
            o3 = fma2(a, mk2(v23.z, v23.w), o3);
        }
        Os[i][h * 4 + 0] = (o0.x + o0.y) * inv;
        Os[i][h * 4 + 1] = (o1.x + o1.y) * inv;
        Os[i][h * 4 + 2] = (o2.x + o2.y) * inv;
        Os[i][h * 4 + 3] = (o3.x + o3.y) * inv;
    }
    __syncthreads();

    // Output projection + store: 4 outputs/thread, vectorized.
    float* outbuf = (axis == 0) ? g_row[out_sel] : g_col[out_sel];
#pragma unroll
    for (int it = 0; it < 4; it++) {
        const int r   = it * 96 + t;
        const int tok = r >> 3, d = r & 7;
        const float4* orow = (const float4*)Os[tok];
        const float4* w    = (const float4*)Wos[d];
        float4 oa = orow[0], ob = orow[1], wa = w[0], wb = w[1];
        float2 acc = mul2(mk2(oa.x, oa.y), mk2(wa.x, wa.y));
        acc = fma2(mk2(oa.z, oa.w), mk2(wa.z, wa.w), acc);
        acc = fma2(mk2(ob.x, ob.y), mk2(wb.x, wb.y), acc);
        acc = fma2(mk2(ob.z, ob.w), mk2(wb.z, wb.w), acc);
        float v = acc.x + acc.y + bos[d];
        const int addr = (axis == 0) ? base + (tok * SS + slice) * DD + d
                                     : base + (slice * SS + tok) * DD + d;
        outbuf[addr] = v;
    }
}

// ---------------------------------------------------------------------------
// Classifier: m[b,i,j] = relu(max_d(o_row+o_col)); logits = m @ cls_w.T + cls_b; softmax
// ---------------------------------------------------------------------------
__global__ __launch_bounds__(256) void cls_kernel(
    const float* __restrict__ cls_w, const float* __restrict__ cls_b,
    float* __restrict__ out, int sel)
{
    const int b = blockIdx.x;
    const int t = threadIdx.x;
    const float* r = g_row[sel];
    const float* c = g_col[sel];
    const int base = b * SS * SS * DD;

    float part[NCLS];
#pragma unroll
    for (int cc = 0; cc < NCLS; cc++) part[cc] = 0.f;

    for (int k = t; k < SS * SS; k += 256) {
        const float4* pr = (const float4*)&r[base + k * 8];
        const float4* pc = (const float4*)&c[base + k * 8];
        float4 r0 = pr[0], r1 = pr[1], c0 = pc[0], c1 = pc[1];
        float m = fmaxf(fmaxf(fmaxf(r0.x + c0.x, r0.y + c0.y), fmaxf(r0.z + c0.z, r0.w + c0.w)),
                        fmaxf(fmaxf(r1.x + c1.x, r1.y + c1.y), fmaxf(r1.z + c1.z, r1.w + c1.w)));
        m = fmaxf(m, 0.f);
#pragma unroll
        for (int cc = 0; cc < NCLS; cc++)
            part[cc] = fmaf(m, cls_w[cc * (SS * SS) + k], part[cc]);
    }

    __shared__ float red[NCLS][256];
#pragma unroll
    for (int cc = 0; cc < NCLS; cc++) red[cc][t] = part[cc];
    __syncthreads();
    for (int off = 128; off > 0; off >>= 1) {
        if (t < off) {
#pragma unroll
            for (int cc = 0; cc < NCLS; cc++) red[cc][t] += red[cc][t + off];
        }
        __syncthreads();
    }
    if (t == 0) {
        float lg[NCLS];
        float mx = -1e30f;
#pragma unroll
        for (int cc = 0; cc < NCLS; cc++) {
            lg[cc] = red[cc][0] + cls_b[cc];
            mx = fmaxf(mx, lg[cc]);
        }
        float s = 0.f;
#pragma unroll
        for (int cc = 0; cc < NCLS; cc++) { lg[cc] = __expf(lg[cc] - mx); s += lg[cc]; }
        float inv = 1.f / s;
#pragma unroll
        for (int cc = 0; cc < NCLS; cc++) out[b * NCLS + cc] = lg[cc] * inv;
    }
}

// ---------------------------------------------------------------------------
extern "C" void kernel_launch(void* const* d_in, const int* in_sizes, int n_in,
                              void* d_out, int out_size)
{
    (void)in_sizes; (void)n_in; (void)out_size;
    const float* x       = (const float*)d_in[0];
    const float* enc_w   = (const float*)d_in[1];
    const float* enc_b   = (const float*)d_in[2];
    const float* pos_row = (const float*)d_in[3];
    const float* pos_col = (const float*)d_in[4];
    const float* Wq      = (const float*)d_in[5];
    const float* Wk      = (const float*)d_in[6];
    const float* Wv      = (const float*)d_in[7];
    const float* Wo      = (const float*)d_in[8];
    const float* bo      = (const float*)d_in[9];
    const float* cls_w   = (const float*)d_in[10];
    const float* cls_b   = (const float*)d_in[11];

    encoder_kernel<<<(BB * SS * SS + 255) / 256, 256>>>(x, enc_w, enc_b, pos_row, pos_col);

    dim3 grid(SS, BB, 2);
    for (int l = 0; l < LL; l++) {
        int in_mode = (l == 0) ? 0 : 1 + ((l - 1) & 1);
        int out_sel = l & 1;
        layer_kernel<<<grid, 96>>>(in_mode, out_sel, Wq, Wk, Wv, Wo, bo, l);
    }

    cls_kernel<<<BB, 256>>>(cls_w, cls_b, (float*)d_out, (LL - 1) & 1);
}